// round 4
// baseline (speedup 1.0000x reference)
#include <cuda_runtime.h>
#include <math.h>
#include <stdint.h>

#define B_TOK 16384
#define D_DIM 1024
#define H_DIM 256
#define E_NUM 8
#define TM    128
#define NTHR  256

// smem plan (bytes from 16B-aligned dynamic base):
//   GEMM1: 3-stage ring, stage = A(16KB)+B(32KB)=48KB  @ 0..147456
//   GEMM2: A2 (gelu h, 128KB) @ 0..131072 ; B ring 3x32KB @ 131072..229376
#define S1_SZ   49152
#define A2_OFF  0
#define B2_OFF  131072
#define B2_SZ   32768
#define DYN_SMEM 229376

// ---------------- device scratch ----------------
__device__ int   g_cnt[E_NUM];
__device__ int   g_tok[E_NUM][B_TOK];          // tok*2 + rank
__device__ float g_wgt[E_NUM][B_TOK];
__device__ float g_xt[(size_t)B_TOK * D_DIM];                 // x in tf32 bits
__device__ float g_w1t[(size_t)E_NUM * H_DIM * D_DIM];        // [e][h][d] tf32
__device__ float g_w2t[(size_t)E_NUM * D_DIM * H_DIM];        // [e][d][h] tf32
__device__ float g_part[2ull * B_TOK * D_DIM];                // rank partials

// ---------------- helpers ----------------
__device__ __forceinline__ uint32_t smem_u32(const void* p) {
    uint32_t r;
    asm("{.reg .u64 t; cvta.to.shared.u64 t,%1; cvt.u32.u64 %0,t;}" : "=r"(r) : "l"(p));
    return r;
}
__device__ __forceinline__ uint32_t f2tf(float f) {
    uint32_t u; asm("cvt.rna.tf32.f32 %0,%1;" : "=r"(u) : "f"(f)); return u;
}
__device__ __forceinline__ void cp16(uint32_t s, const void* g) {
    asm volatile("cp.async.cg.shared.global [%0],[%1],16;" :: "r"(s), "l"(g));
}
__device__ __forceinline__ void cp_commit() {
    asm volatile("cp.async.commit_group;" ::: "memory");
}
template <int N> __device__ __forceinline__ void cp_wait() {
    asm volatile("cp.async.wait_group %0;" :: "n"(N) : "memory");
}
// 8x8 b16 ldmatrix == 8x4 f32 tile, thread t -> [t/4][t%4]: exact tf32 frag map
__device__ __forceinline__ void ldsm4(uint32_t* r, uint32_t a) {
    asm volatile("ldmatrix.sync.aligned.m8n8.x4.shared.b16 {%0,%1,%2,%3},[%4];"
                 : "=r"(r[0]), "=r"(r[1]), "=r"(r[2]), "=r"(r[3]) : "r"(a));
}
__device__ __forceinline__ void mma8(float* c, const uint32_t* a, const uint32_t* b) {
    asm volatile(
        "mma.sync.aligned.m16n8k8.row.col.f32.tf32.tf32.f32 "
        "{%0,%1,%2,%3},{%4,%5,%6,%7},{%8,%9},{%0,%1,%2,%3};"
        : "+f"(c[0]), "+f"(c[1]), "+f"(c[2]), "+f"(c[3])
        : "r"(a[0]), "r"(a[1]), "r"(a[2]), "r"(a[3]), "r"(b[0]), "r"(b[1]));
}

// ---------------- weight transpose + tf32 convert ----------------
__global__ void transpose_tf32_kernel(const float* __restrict__ src,
                                      float* __restrict__ dst, int R, int C, int do_zero) {
    __shared__ float tile[32][33];
    if (do_zero && blockIdx.x == 0 && blockIdx.y == 0 && blockIdx.z == 0 &&
        threadIdx.y == 0 && threadIdx.x < E_NUM)
        g_cnt[threadIdx.x] = 0;
    const int e = blockIdx.z;
    const int r0 = blockIdx.y * 32, c0 = blockIdx.x * 32;
    src += (size_t)e * R * C;
    dst += (size_t)e * R * C;
    const int tx = threadIdx.x, ty = threadIdx.y;
#pragma unroll
    for (int dy = 0; dy < 32; dy += 8)
        tile[ty + dy][tx] = src[(size_t)(r0 + ty + dy) * C + c0 + tx];
    __syncthreads();
#pragma unroll
    for (int dy = 0; dy < 32; dy += 8)
        dst[(size_t)(c0 + ty + dy) * R + r0 + tx] = __uint_as_float(f2tf(tile[tx][ty + dy]));
}

// ---------------- gate: logits, top-2, scatter; also writes x as tf32 ----------------
__global__ __launch_bounds__(512) void gate_kernel(
    const float* __restrict__ x, const float* __restrict__ gw,
    const float* __restrict__ gb)
{
    __shared__ float gws[E_NUM * D_DIM];
    const int tid = threadIdx.x;
    for (int i = tid; i < E_NUM * D_DIM; i += 512) {
        int e = i >> 10, d = i & 1023;
        gws[i] = gw[d * E_NUM + e];
    }
    __syncthreads();

    const int warp = tid >> 5, lane = tid & 31;
    const int tok0 = blockIdx.x * 64 + warp * 4;

    float acc[4][E_NUM];
#pragma unroll
    for (int t = 0; t < 4; t++)
#pragma unroll
        for (int e = 0; e < E_NUM; e++) acc[t][e] = 0.f;

    const float* xr  = x    + (size_t)tok0 * D_DIM;
    float*       xtr = g_xt + (size_t)tok0 * D_DIM;
    for (int d = lane; d < D_DIM; d += 32) {
        float xv[4];
#pragma unroll
        for (int t = 0; t < 4; t++) {
            xv[t] = xr[(size_t)t * D_DIM + d];
            xtr[(size_t)t * D_DIM + d] = __uint_as_float(f2tf(xv[t]));
        }
#pragma unroll
        for (int e = 0; e < E_NUM; e++) {
            float w = gws[e * D_DIM + d];
#pragma unroll
            for (int t = 0; t < 4; t++) acc[t][e] += xv[t] * w;
        }
    }
#pragma unroll
    for (int t = 0; t < 4; t++)
#pragma unroll
        for (int e = 0; e < E_NUM; e++)
#pragma unroll
            for (int s = 16; s; s >>= 1)
                acc[t][e] += __shfl_xor_sync(0xffffffffu, acc[t][e], s);

    if (lane == 0) {
#pragma unroll
        for (int t = 0; t < 4; t++) {
            float l[E_NUM];
#pragma unroll
            for (int e = 0; e < E_NUM; e++) l[e] = acc[t][e] + gb[e];
            int i0 = 0;
#pragma unroll
            for (int e = 1; e < E_NUM; e++) if (l[e] > l[i0]) i0 = e;
            int i1 = (i0 == 0) ? 1 : 0;
#pragma unroll
            for (int e = 0; e < E_NUM; e++) if (e != i0 && l[e] > l[i1]) i1 = e;
            float e1 = expf(l[i1] - l[i0]);
            float s  = 1.0f + e1;
            int tok  = tok0 + t;
            int p0 = atomicAdd(&g_cnt[i0], 1);
            g_tok[i0][p0] = tok * 2 + 0; g_wgt[i0][p0] = 1.0f / s;
            int p1 = atomicAdd(&g_cnt[i1], 1);
            g_tok[i1][p1] = tok * 2 + 1; g_wgt[i1][p1] = e1 / s;
        }
    }
}

// ---------------- expert MLP: 128x256 tile, 3-stage pipeline, 1 sync/slice ----------------
__global__ void __launch_bounds__(NTHR, 1) expert_kernel(
    const float* __restrict__ b1, const float* __restrict__ b2)
{
    const int e     = blockIdx.y;
    const int cnt   = g_cnt[e];
    const int start = blockIdx.x * TM;
    if (start >= cnt) return;
    const int mcount = min(TM, cnt - start);

    __shared__ int   tids_s[TM];
    __shared__ float wts_s[TM];
    extern __shared__ __align__(16) char smem[];
    const uint32_t sb = smem_u32(smem);

    const int tid = threadIdx.x;
    if (tid < TM) {
        bool v = tid < mcount;
        int  src = v ? (start + tid) : start;
        tids_s[tid] = g_tok[e][src];
        wts_s[tid]  = v ? g_wgt[e][src] : 0.f;
    }
    __syncthreads();

    const int warp = tid >> 5, lane = tid & 31;
    const int wm = warp & 1, wn = warp >> 1;
    const int sub = lane >> 3, rin = lane & 7;
    const int g = lane >> 2, tg = lane & 3;
    const int arl = (sub & 1) * 8 + rin, auo = sub >> 1;
    const int brl = ((sub >> 1) & 1) * 8 + rin, buo = sub & 1;

    const float* w1e = g_w1t + (size_t)e * H_DIM * D_DIM;
    const float* w2e = g_w2t + (size_t)e * D_DIM * H_DIM;
    const float* b1e = b1 + e * H_DIM;
    const float* b2e = b2 + e * D_DIM;

    auto load1 = [&](int slice, int st) {      // slice k0 = slice*32
        const int k0 = slice * 32;
        const uint32_t Ab = sb + st * S1_SZ;
        const uint32_t Bb = Ab + 16384;
#pragma unroll
        for (int t = 0; t < 4; t++) {
            int idx = tid + t * NTHR, r = idx >> 3, u = idx & 7;
            int raw = tids_s[r];
            cp16(Ab + r * 128 + ((u ^ (r & 7)) << 4),
                 g_xt + (size_t)(raw >> 1) * D_DIM + k0 + u * 4);
        }
#pragma unroll
        for (int t = 0; t < 8; t++) {
            int idx = tid + t * NTHR, r = idx >> 3, u = idx & 7;
            cp16(Bb + r * 128 + ((u ^ (r & 7)) << 4),
                 w1e + (size_t)r * D_DIM + k0 + u * 4);
        }
        cp_commit();
    };
    auto load2 = [&](int sc, int st) {         // sc = n2*8 + s
        const int n2 = sc >> 3, s = sc & 7;
        const uint32_t Bb = sb + B2_OFF + st * B2_SZ;
#pragma unroll
        for (int t = 0; t < 8; t++) {
            int idx = tid + t * NTHR, r = idx >> 3, u = idx & 7;
            cp16(Bb + r * 128 + ((u ^ (r & 7)) << 4),
                 w2e + (size_t)(n2 * 256 + r) * H_DIM + s * 32 + u * 4);
        }
        cp_commit();
    };

    float c[4][8][4];
#pragma unroll
    for (int mi = 0; mi < 4; mi++)
#pragma unroll
        for (int ni = 0; ni < 8; ni++)
#pragma unroll
            for (int q = 0; q < 4; q++) c[mi][ni][q] = 0.f;

    // =============== GEMM1: h = x_tile[128,1024] @ w1^T ===============
    load1(0, 0);
    load1(1, 1);
    for (int i = 0; i < 32; i++) {
        if (i < 31) cp_wait<1>(); else cp_wait<0>();
        __syncthreads();
        if (i + 2 < 32) load1(i + 2, (i + 2) % 3);
        const uint32_t Ab = sb + (i % 3) * S1_SZ;
        const uint32_t Bb = Ab + 16384;
#pragma unroll
        for (int kk = 0; kk < 4; kk++) {
            uint32_t a[4][4], bf[4][4];
#pragma unroll
            for (int mi = 0; mi < 4; mi++) {
                int row = wm * 64 + mi * 16 + arl;
                int u   = 2 * kk + auo;
                ldsm4(a[mi], Ab + row * 128 + ((u ^ (row & 7)) << 4));
            }
#pragma unroll
            for (int p = 0; p < 4; p++) {
                int row = wn * 64 + p * 16 + brl;
                int u   = 2 * kk + buo;
                ldsm4(bf[p], Bb + row * 128 + ((u ^ (row & 7)) << 4));
            }
#pragma unroll
            for (int mi = 0; mi < 4; mi++)
#pragma unroll
                for (int ni = 0; ni < 8; ni++)
                    mma8(c[mi][ni], a[mi], &bf[ni >> 1][(ni & 1) * 2]);
        }
    }

    // GEMM2 B prologue: safe pre-sync (targets 128K..196K; live GEMM1 stages are 0..96K)
    load2(0, 0);
    load2(1, 1);
    __syncthreads();   // all warps done with GEMM1 stages before A2 overwrite

    // =============== epilogue1: bias + exact gelu -> A2 (tf32, swizzled) ===============
#pragma unroll
    for (int mi = 0; mi < 4; mi++) {
#pragma unroll
        for (int ni = 0; ni < 8; ni++) {
            int col = wn * 64 + ni * 8 + tg * 2;
            float bb0 = b1e[col], bb1 = b1e[col + 1];
            int u = col >> 2, bo = (col & 3) * 4;
#pragma unroll
            for (int h = 0; h < 2; h++) {
                int row = wm * 64 + mi * 16 + g + h * 8;
                float v0 = c[mi][ni][h * 2]     + bb0;
                float v1 = c[mi][ni][h * 2 + 1] + bb1;
                v0 = 0.5f * v0 * (1.0f + erff(v0 * 0.70710678f));
                v1 = 0.5f * v1 * (1.0f + erff(v1 * 0.70710678f));
                uint32_t addr = sb + A2_OFF + row * 1024 + ((u ^ (row & 7)) << 4) + bo;
                asm volatile("st.shared.v2.b32 [%0],{%1,%2};"
                             :: "r"(addr), "r"(f2tf(v0)), "r"(f2tf(v1)));
            }
        }
    }
    __syncthreads();

    // =============== GEMM2: out = gelu(h)[128,256] @ w2^T, 4 N-panels ===============
    for (int sc = 0; sc < 32; sc++) {
        const int n2 = sc >> 3, s = sc & 7;
        if (sc < 31) cp_wait<1>(); else cp_wait<0>();
        __syncthreads();
        if (sc + 2 < 32) load2(sc + 2, (sc + 2) % 3);
        if (s == 0) {
#pragma unroll
            for (int mi = 0; mi < 4; mi++)
#pragma unroll
                for (int ni = 0; ni < 8; ni++)
#pragma unroll
                    for (int q = 0; q < 4; q++) c[mi][ni][q] = 0.f;
        }
        const uint32_t Bb = sb + B2_OFF + (sc % 3) * B2_SZ;
#pragma unroll
        for (int kk = 0; kk < 4; kk++) {
            uint32_t a[4][4], bf[4][4];
#pragma unroll
            for (int mi = 0; mi < 4; mi++) {
                int row = wm * 64 + mi * 16 + arl;
                int u   = s * 8 + 2 * kk + auo;
                ldsm4(a[mi], sb + A2_OFF + row * 1024 + ((u ^ (row & 7)) << 4));
            }
#pragma unroll
            for (int p = 0; p < 4; p++) {
                int row = wn * 64 + p * 16 + brl;
                int u   = 2 * kk + buo;
                ldsm4(bf[p], Bb + row * 128 + ((u ^ (row & 7)) << 4));
            }
#pragma unroll
            for (int mi = 0; mi < 4; mi++)
#pragma unroll
                for (int ni = 0; ni < 8; ni++)
                    mma8(c[mi][ni], a[mi], &bf[ni >> 1][(ni & 1) * 2]);
        }

        if (s == 7) {   // panel complete: weighted store to rank partials
#pragma unroll
            for (int mi = 0; mi < 4; mi++) {
#pragma unroll
                for (int h = 0; h < 2; h++) {
                    int r = wm * 64 + mi * 16 + g + h * 8;
                    if (r < mcount) {
                        int   raw = tids_s[r];
                        float wt  = wts_s[r];
                        float* dst = g_part + (size_t)(raw & 1) * ((size_t)B_TOK * D_DIM)
                                   + (size_t)(raw >> 1) * D_DIM;
#pragma unroll
                        for (int ni = 0; ni < 8; ni++) {
                            int col = n2 * 256 + wn * 64 + ni * 8 + tg * 2;
                            float v0 = (c[mi][ni][h * 2]     + b2e[col])     * wt;
                            float v1 = (c[mi][ni][h * 2 + 1] + b2e[col + 1]) * wt;
                            *(float2*)(dst + col) = make_float2(v0, v1);
                        }
                    }
                }
            }
        }
    }
}

// ---------------- combine: out = part0 + part1 ----------------
__global__ __launch_bounds__(256) void combine_kernel(float* __restrict__ out) {
    size_t i = ((size_t)blockIdx.x * 256 + threadIdx.x) * 4;
    float4 a = *(const float4*)(g_part + i);
    float4 b = *(const float4*)(g_part + (size_t)B_TOK * D_DIM + i);
    *(float4*)(out + i) = make_float4(a.x + b.x, a.y + b.y, a.z + b.z, a.w + b.w);
}

// ---------------- launch ----------------
extern "C" void kernel_launch(void* const* d_in, const int* in_sizes, int n_in,
                              void* d_out, int out_size) {
    const float* x  = (const float*)d_in[0];
    const float* gw = (const float*)d_in[1];
    const float* gb = (const float*)d_in[2];
    const float* w1 = (const float*)d_in[3];
    const float* b1 = (const float*)d_in[4];
    const float* w2 = (const float*)d_in[5];
    const float* b2 = (const float*)d_in[6];
    float* out = (float*)d_out;

    static float* w1t_ptr = nullptr;
    static float* w2t_ptr = nullptr;
    if (!w1t_ptr) {
        cudaGetSymbolAddress((void**)&w1t_ptr, g_w1t);
        cudaGetSymbolAddress((void**)&w2t_ptr, g_w2t);
        cudaFuncSetAttribute(expert_kernel,
                             cudaFuncAttributeMaxDynamicSharedMemorySize, DYN_SMEM);
    }

    transpose_tf32_kernel<<<dim3(H_DIM / 32, D_DIM / 32, E_NUM), dim3(32, 8)>>>(
        w1, w1t_ptr, D_DIM, H_DIM, 1);
    transpose_tf32_kernel<<<dim3(D_DIM / 32, H_DIM / 32, E_NUM), dim3(32, 8)>>>(
        w2, w2t_ptr, H_DIM, D_DIM, 0);
    gate_kernel<<<B_TOK / 64, 512>>>(x, gw, gb);
    expert_kernel<<<dim3(B_TOK / TM, E_NUM), NTHR, DYN_SMEM>>>(b1, b2);
    combine_kernel<<<B_TOK * D_DIM / 1024, 256>>>(out);
}

// round 5
// speedup vs baseline: 1.0354x; 1.0354x over previous
#include <cuda_runtime.h>
#include <math.h>
#include <stdint.h>

#define B_TOK 16384
#define D_DIM 1024
#define H_DIM 256
#define E_NUM 8
#define TM    128
#define NTHR  512

// smem plan (bytes from 16B-aligned dynamic base):
//   GEMM1: 3-stage ring, stage = A(16KB)+B(32KB)=48KB  @ 0..147456
//   GEMM2: A2 (gelu h, 128KB) @ 0..131072 ; B ring 3x32KB @ 131072..229376
#define S1_SZ   49152
#define A2_OFF  0
#define B2_OFF  131072
#define B2_SZ   32768
#define DYN_SMEM 229376

// ---------------- device scratch ----------------
__device__ int   g_cnt[E_NUM];
__device__ int   g_tok[E_NUM][B_TOK];          // tok*2 + rank
__device__ float g_wgt[E_NUM][B_TOK];
__device__ float g_xt[(size_t)B_TOK * D_DIM];                 // x in tf32 bits
__device__ float g_w1t[(size_t)E_NUM * H_DIM * D_DIM];        // [e][h][d] tf32
__device__ float g_w2t[(size_t)E_NUM * D_DIM * H_DIM];        // [e][d][h] tf32
__device__ float g_part[2ull * B_TOK * D_DIM];                // rank partials

// ---------------- helpers ----------------
__device__ __forceinline__ uint32_t smem_u32(const void* p) {
    uint32_t r;
    asm("{.reg .u64 t; cvta.to.shared.u64 t,%1; cvt.u32.u64 %0,t;}" : "=r"(r) : "l"(p));
    return r;
}
__device__ __forceinline__ uint32_t f2tf(float f) {
    uint32_t u; asm("cvt.rna.tf32.f32 %0,%1;" : "=r"(u) : "f"(f)); return u;
}
__device__ __forceinline__ void cp16(uint32_t s, const void* g) {
    asm volatile("cp.async.cg.shared.global [%0],[%1],16;" :: "r"(s), "l"(g));
}
__device__ __forceinline__ void cp_commit() {
    asm volatile("cp.async.commit_group;" ::: "memory");
}
template <int N> __device__ __forceinline__ void cp_wait() {
    asm volatile("cp.async.wait_group %0;" :: "n"(N) : "memory");
}
// 8x8 b16 ldmatrix == 8x4 f32 tile, thread t -> [t/4][t%4]: exact tf32 frag map
__device__ __forceinline__ void ldsm4(uint32_t* r, uint32_t a) {
    asm volatile("ldmatrix.sync.aligned.m8n8.x4.shared.b16 {%0,%1,%2,%3},[%4];"
                 : "=r"(r[0]), "=r"(r[1]), "=r"(r[2]), "=r"(r[3]) : "r"(a));
}
__device__ __forceinline__ void mma8(float* c, const uint32_t* a, const uint32_t* b) {
    asm volatile(
        "mma.sync.aligned.m16n8k8.row.col.f32.tf32.tf32.f32 "
        "{%0,%1,%2,%3},{%4,%5,%6,%7},{%8,%9},{%0,%1,%2,%3};"
        : "+f"(c[0]), "+f"(c[1]), "+f"(c[2]), "+f"(c[3])
        : "r"(a[0]), "r"(a[1]), "r"(a[2]), "r"(a[3]), "r"(b[0]), "r"(b[1]));
}

// ---------------- weight transpose + tf32 convert ----------------
__global__ void transpose_tf32_kernel(const float* __restrict__ src,
                                      float* __restrict__ dst, int R, int C, int do_zero) {
    __shared__ float tile[32][33];
    if (do_zero && blockIdx.x == 0 && blockIdx.y == 0 && blockIdx.z == 0 &&
        threadIdx.y == 0 && threadIdx.x < E_NUM)
        g_cnt[threadIdx.x] = 0;
    const int e = blockIdx.z;
    const int r0 = blockIdx.y * 32, c0 = blockIdx.x * 32;
    src += (size_t)e * R * C;
    dst += (size_t)e * R * C;
    const int tx = threadIdx.x, ty = threadIdx.y;
#pragma unroll
    for (int dy = 0; dy < 32; dy += 8)
        tile[ty + dy][tx] = src[(size_t)(r0 + ty + dy) * C + c0 + tx];
    __syncthreads();
#pragma unroll
    for (int dy = 0; dy < 32; dy += 8)
        dst[(size_t)(c0 + ty + dy) * R + r0 + tx] = __uint_as_float(f2tf(tile[tx][ty + dy]));
}

// ---------------- gate: logits, top-2, scatter; also writes x as tf32 ----------------
__global__ __launch_bounds__(512) void gate_kernel(
    const float* __restrict__ x, const float* __restrict__ gw,
    const float* __restrict__ gb)
{
    __shared__ float gws[E_NUM * D_DIM];
    const int tid = threadIdx.x;
    for (int i = tid; i < E_NUM * D_DIM; i += 512) {
        int e = i >> 10, d = i & 1023;
        gws[i] = gw[d * E_NUM + e];
    }
    __syncthreads();

    const int warp = tid >> 5, lane = tid & 31;
    const int tok0 = blockIdx.x * 64 + warp * 4;

    float acc[4][E_NUM];
#pragma unroll
    for (int t = 0; t < 4; t++)
#pragma unroll
        for (int e = 0; e < E_NUM; e++) acc[t][e] = 0.f;

    const float* xr  = x    + (size_t)tok0 * D_DIM;
    float*       xtr = g_xt + (size_t)tok0 * D_DIM;
    for (int d = lane; d < D_DIM; d += 32) {
        float xv[4];
#pragma unroll
        for (int t = 0; t < 4; t++) {
            xv[t] = xr[(size_t)t * D_DIM + d];
            xtr[(size_t)t * D_DIM + d] = __uint_as_float(f2tf(xv[t]));
        }
#pragma unroll
        for (int e = 0; e < E_NUM; e++) {
            float w = gws[e * D_DIM + d];
#pragma unroll
            for (int t = 0; t < 4; t++) acc[t][e] += xv[t] * w;
        }
    }
#pragma unroll
    for (int t = 0; t < 4; t++)
#pragma unroll
        for (int e = 0; e < E_NUM; e++)
#pragma unroll
            for (int s = 16; s; s >>= 1)
                acc[t][e] += __shfl_xor_sync(0xffffffffu, acc[t][e], s);

    if (lane == 0) {
#pragma unroll
        for (int t = 0; t < 4; t++) {
            float l[E_NUM];
#pragma unroll
            for (int e = 0; e < E_NUM; e++) l[e] = acc[t][e] + gb[e];
            int i0 = 0;
#pragma unroll
            for (int e = 1; e < E_NUM; e++) if (l[e] > l[i0]) i0 = e;
            int i1 = (i0 == 0) ? 1 : 0;
#pragma unroll
            for (int e = 0; e < E_NUM; e++) if (e != i0 && l[e] > l[i1]) i1 = e;
            float e1 = expf(l[i1] - l[i0]);
            float s  = 1.0f + e1;
            int tok  = tok0 + t;
            int p0 = atomicAdd(&g_cnt[i0], 1);
            g_tok[i0][p0] = tok * 2 + 0; g_wgt[i0][p0] = 1.0f / s;
            int p1 = atomicAdd(&g_cnt[i1], 1);
            g_tok[i1][p1] = tok * 2 + 1; g_wgt[i1][p1] = e1 / s;
        }
    }
}

// ---------------- expert MLP: 128x256 tile, 16 warps (32x64 each), 3-stage pipe ----------------
__global__ void __launch_bounds__(NTHR, 1) expert_kernel(
    const float* __restrict__ b1, const float* __restrict__ b2)
{
    const int e     = blockIdx.y;
    const int cnt   = g_cnt[e];
    const int start = blockIdx.x * TM;
    if (start >= cnt) return;
    const int mcount = min(TM, cnt - start);

    __shared__ int   tids_s[TM];
    __shared__ float wts_s[TM];
    extern __shared__ __align__(16) char smem[];
    const uint32_t sb = smem_u32(smem);

    const int tid = threadIdx.x;
    if (tid < TM) {
        bool v = tid < mcount;
        int  src = v ? (start + tid) : start;
        tids_s[tid] = g_tok[e][src];
        wts_s[tid]  = v ? g_wgt[e][src] : 0.f;
    }
    __syncthreads();

    const int warp = tid >> 5, lane = tid & 31;
    const int wm = warp & 3, wn = warp >> 2;        // 4(M,32 rows) x 4(N,64 cols)
    const int sub = lane >> 3, rin = lane & 7;
    const int g = lane >> 2, tg = lane & 3;
    const int arl = (sub & 1) * 8 + rin, auo = sub >> 1;
    const int brl = ((sub >> 1) & 1) * 8 + rin, buo = sub & 1;

    const float* w1e = g_w1t + (size_t)e * H_DIM * D_DIM;
    const float* w2e = g_w2t + (size_t)e * D_DIM * H_DIM;
    const float* b1e = b1 + e * H_DIM;
    const float* b2e = b2 + e * D_DIM;

    auto load1 = [&](int slice, int st) {      // slice k0 = slice*32
        const int k0 = slice * 32;
        const uint32_t Ab = sb + st * S1_SZ;
        const uint32_t Bb = Ab + 16384;
#pragma unroll
        for (int t = 0; t < 2; t++) {          // A: 128 rows x 8 units = 1024 cp16
            int idx = tid + t * NTHR, r = idx >> 3, u = idx & 7;
            int raw = tids_s[r];
            cp16(Ab + r * 128 + ((u ^ (r & 7)) << 4),
                 g_xt + (size_t)(raw >> 1) * D_DIM + k0 + u * 4);
        }
#pragma unroll
        for (int t = 0; t < 4; t++) {          // B: 256 rows x 8 units = 2048 cp16
            int idx = tid + t * NTHR, r = idx >> 3, u = idx & 7;
            cp16(Bb + r * 128 + ((u ^ (r & 7)) << 4),
                 w1e + (size_t)r * D_DIM + k0 + u * 4);
        }
        cp_commit();
    };
    auto load2 = [&](int sc, int st) {         // sc = n2*8 + s
        const int n2 = sc >> 3, s = sc & 7;
        const uint32_t Bb = sb + B2_OFF + st * B2_SZ;
#pragma unroll
        for (int t = 0; t < 4; t++) {
            int idx = tid + t * NTHR, r = idx >> 3, u = idx & 7;
            cp16(Bb + r * 128 + ((u ^ (r & 7)) << 4),
                 w2e + (size_t)(n2 * 256 + r) * H_DIM + s * 32 + u * 4);
        }
        cp_commit();
    };

    float c[2][8][4];
#pragma unroll
    for (int mi = 0; mi < 2; mi++)
#pragma unroll
        for (int ni = 0; ni < 8; ni++)
#pragma unroll
            for (int q = 0; q < 4; q++) c[mi][ni][q] = 0.f;

    // =============== GEMM1: h = x_tile[128,1024] @ w1^T ===============
    load1(0, 0);
    load1(1, 1);
    for (int i = 0; i < 32; i++) {
        if (i < 31) cp_wait<1>(); else cp_wait<0>();
        __syncthreads();
        if (i + 2 < 32) load1(i + 2, (i + 2) % 3);
        const uint32_t Ab = sb + (i % 3) * S1_SZ;
        const uint32_t Bb = Ab + 16384;
#pragma unroll
        for (int kk = 0; kk < 4; kk++) {
            uint32_t a[2][4], bf[4][4];
#pragma unroll
            for (int mi = 0; mi < 2; mi++) {
                int row = wm * 32 + mi * 16 + arl;
                int u   = 2 * kk + auo;
                ldsm4(a[mi], Ab + row * 128 + ((u ^ (row & 7)) << 4));
            }
#pragma unroll
            for (int p = 0; p < 4; p++) {
                int row = wn * 64 + p * 16 + brl;
                int u   = 2 * kk + buo;
                ldsm4(bf[p], Bb + row * 128 + ((u ^ (row & 7)) << 4));
            }
#pragma unroll
            for (int mi = 0; mi < 2; mi++)
#pragma unroll
                for (int ni = 0; ni < 8; ni++)
                    mma8(c[mi][ni], a[mi], &bf[ni >> 1][(ni & 1) * 2]);
        }
    }

    // GEMM2 B prologue: safe pre-sync (targets 128K..196K; live GEMM1 stages are 0..96K)
    load2(0, 0);
    load2(1, 1);
    __syncthreads();   // all warps done with GEMM1 stages before A2 overwrite

    // =============== epilogue1: bias + exact gelu -> A2 (tf32, swizzled) ===============
#pragma unroll
    for (int mi = 0; mi < 2; mi++) {
#pragma unroll
        for (int ni = 0; ni < 8; ni++) {
            int col = wn * 64 + ni * 8 + tg * 2;
            float bb0 = b1e[col], bb1 = b1e[col + 1];
            int u = col >> 2, bo = (col & 3) * 4;
#pragma unroll
            for (int h = 0; h < 2; h++) {
                int row = wm * 32 + mi * 16 + g + h * 8;
                float v0 = c[mi][ni][h * 2]     + bb0;
                float v1 = c[mi][ni][h * 2 + 1] + bb1;
                v0 = 0.5f * v0 * (1.0f + erff(v0 * 0.70710678f));
                v1 = 0.5f * v1 * (1.0f + erff(v1 * 0.70710678f));
                uint32_t addr = sb + A2_OFF + row * 1024 + ((u ^ (row & 7)) << 4) + bo;
                asm volatile("st.shared.v2.b32 [%0],{%1,%2};"
                             :: "r"(addr), "r"(f2tf(v0)), "r"(f2tf(v1)));
            }
        }
    }
    __syncthreads();

    // =============== GEMM2: out = gelu(h)[128,256] @ w2^T, 4 N-panels ===============
    for (int sc = 0; sc < 32; sc++) {
        const int n2 = sc >> 3, s = sc & 7;
        if (sc < 31) cp_wait<1>(); else cp_wait<0>();
        __syncthreads();
        if (sc + 2 < 32) load2(sc + 2, (sc + 2) % 3);
        if (s == 0) {
#pragma unroll
            for (int mi = 0; mi < 2; mi++)
#pragma unroll
                for (int ni = 0; ni < 8; ni++)
#pragma unroll
                    for (int q = 0; q < 4; q++) c[mi][ni][q] = 0.f;
        }
        const uint32_t Bb = sb + B2_OFF + (sc % 3) * B2_SZ;
#pragma unroll
        for (int kk = 0; kk < 4; kk++) {
            uint32_t a[2][4], bf[4][4];
#pragma unroll
            for (int mi = 0; mi < 2; mi++) {
                int row = wm * 32 + mi * 16 + arl;
                int u   = s * 8 + 2 * kk + auo;
                ldsm4(a[mi], sb + A2_OFF + row * 1024 + ((u ^ (row & 7)) << 4));
            }
#pragma unroll
            for (int p = 0; p < 4; p++) {
                int row = wn * 64 + p * 16 + brl;
                int u   = 2 * kk + buo;
                ldsm4(bf[p], Bb + row * 128 + ((u ^ (row & 7)) << 4));
            }
#pragma unroll
            for (int mi = 0; mi < 2; mi++)
#pragma unroll
                for (int ni = 0; ni < 8; ni++)
                    mma8(c[mi][ni], a[mi], &bf[ni >> 1][(ni & 1) * 2]);
        }

        if (s == 7) {   // panel complete: weighted store to rank partials
#pragma unroll
            for (int mi = 0; mi < 2; mi++) {
#pragma unroll
                for (int h = 0; h < 2; h++) {
                    int r = wm * 32 + mi * 16 + g + h * 8;
                    if (r < mcount) {
                        int   raw = tids_s[r];
                        float wt  = wts_s[r];
                        float* dst = g_part + (size_t)(raw & 1) * ((size_t)B_TOK * D_DIM)
                                   + (size_t)(raw >> 1) * D_DIM;
#pragma unroll
                        for (int ni = 0; ni < 8; ni++) {
                            int col = n2 * 256 + wn * 64 + ni * 8 + tg * 2;
                            float v0 = (c[mi][ni][h * 2]     + b2e[col])     * wt;
                            float v1 = (c[mi][ni][h * 2 + 1] + b2e[col + 1]) * wt;
                            *(float2*)(dst + col) = make_float2(v0, v1);
                        }
                    }
                }
            }
        }
    }
}

// ---------------- combine: out = part0 + part1 ----------------
__global__ __launch_bounds__(256) void combine_kernel(float* __restrict__ out) {
    size_t i = ((size_t)blockIdx.x * 256 + threadIdx.x) * 4;
    float4 a = *(const float4*)(g_part + i);
    float4 b = *(const float4*)(g_part + (size_t)B_TOK * D_DIM + i);
    *(float4*)(out + i) = make_float4(a.x + b.x, a.y + b.y, a.z + b.z, a.w + b.w);
}

// ---------------- launch ----------------
extern "C" void kernel_launch(void* const* d_in, const int* in_sizes, int n_in,
                              void* d_out, int out_size) {
    const float* x  = (const float*)d_in[0];
    const float* gw = (const float*)d_in[1];
    const float* gb = (const float*)d_in[2];
    const float* w1 = (const float*)d_in[3];
    const float* b1 = (const float*)d_in[4];
    const float* w2 = (const float*)d_in[5];
    const float* b2 = (const float*)d_in[6];
    float* out = (float*)d_out;

    static float* w1t_ptr = nullptr;
    static float* w2t_ptr = nullptr;
    if (!w1t_ptr) {
        cudaGetSymbolAddress((void**)&w1t_ptr, g_w1t);
        cudaGetSymbolAddress((void**)&w2t_ptr, g_w2t);
        cudaFuncSetAttribute(expert_kernel,
                             cudaFuncAttributeMaxDynamicSharedMemorySize, DYN_SMEM);
    }

    transpose_tf32_kernel<<<dim3(H_DIM / 32, D_DIM / 32, E_NUM), dim3(32, 8)>>>(
        w1, w1t_ptr, D_DIM, H_DIM, 1);
    transpose_tf32_kernel<<<dim3(D_DIM / 32, H_DIM / 32, E_NUM), dim3(32, 8)>>>(
        w2, w2t_ptr, H_DIM, D_DIM, 0);
    gate_kernel<<<B_TOK / 64, 512>>>(x, gw, gb);
    expert_kernel<<<dim3(B_TOK / TM, E_NUM), NTHR, DYN_SMEM>>>(b1, b2);
    combine_kernel<<<B_TOK * D_DIM / 1024, 256>>>(out);
}